// round 7
// baseline (speedup 1.0000x reference)
#include <cuda_runtime.h>
#include <math.h>

#define BB 4
#define LL 1024
#define HH 768
#define NHH 12
#define EE 32
#define MPE 4
#define EMM 128
#define KLNK 16
#define TYPED 20
#define NROWS 336
#define FF (HH + TYPED)      // 788
#define NA 160

typedef unsigned long long ull;

// scratch
__device__ float g_att[BB * EMM * LL];          // mention head-mean att rows
__device__ float g_rs[BB * EMM];                // mention row sums
__device__ float g_part[3][BB][EMM][HH];        // split-K raw GEMM partials

__device__ __forceinline__ void fma2(ull& d, ull a, ull b) {
    asm("fma.rn.f32x2 %0, %1, %2, %0;" : "+l"(d) : "l"(a), "l"(b));
}
__device__ __forceinline__ ull dup2(float a) {
    ull d;
    asm("mov.b64 %0, {%1, %1};" : "=l"(d) : "f"(a));
    return d;
}

// ---------------------------------------------------------------------------
// K1: mention attention rows (head mean) + row sums. 512 blocks.
// ---------------------------------------------------------------------------
__global__ void __launch_bounds__(256) k_ment(const float* __restrict__ att,
                                              const int* __restrict__ mpos) {
    __shared__ float red[8];
    int i = blockIdx.x;
    int m = i & 127, b = i >> 7;
    int tid = threadIdx.x;
    int p = mpos[b * EMM + m] + 1;
    const float* rp = att + (size_t)b * NHH * LL * LL + (size_t)p * LL + tid * 4;

    float4 acc = make_float4(0.f, 0.f, 0.f, 0.f);
#pragma unroll
    for (int h = 0; h < NHH; h++) {
        float4 v = *(const float4*)(rp + (size_t)h * LL * LL);
        acc.x += v.x; acc.y += v.y; acc.z += v.z; acc.w += v.w;
    }
    const float inv12 = 1.f / 12.f;
    acc.x *= inv12; acc.y *= inv12; acc.z *= inv12; acc.w *= inv12;
    *(float4*)&g_att[((size_t)b * EMM + m) * LL + tid * 4] = acc;

    float s = (acc.x + acc.y) + (acc.z + acc.w);
#pragma unroll
    for (int off = 16; off > 0; off >>= 1)
        s += __shfl_down_sync(0xffffffffu, s, off);
    if ((tid & 31) == 0) red[tid >> 5] = s;
    __syncthreads();
    if (tid == 0) {
        float t = 0.f;
#pragma unroll
        for (int ww = 0; ww < 8; ww++) t += red[ww];        // fixed order
        g_rs[b * EMM + m] = t;
    }
}

// ---------------------------------------------------------------------------
// K2 "main": GEMM blocks [0,144) + link blocks [144,208) + node blocks
// [208,848). Shared 48KB pool aliased between GEMM tiles and link scratch.
//
// GEMM: split-K raw context GEMM over mention rows (f32x2 FMA).
//   Tile 64n x 128h, TL=32. Warp = 8 n-rows, lane = 4 h.
//   g_part[s][b][m][h] = sum_{l in chunk s} g_att[b][m][l] * seq[b][l][h]
// ---------------------------------------------------------------------------
#define CTN 64
#define CTH 128
#define CTL 32
__global__ void __launch_bounds__(256) k_main(
    const float* __restrict__ att, const float* __restrict__ seq,
    const float* __restrict__ ttab, const int* __restrict__ mpos,
    const int* __restrict__ lstart, const int* __restrict__ llen,
    float* __restrict__ out)
{
    __shared__ __align__(16) float pool[12288];   // 48KB
    int bid = blockIdx.x;
    int tid = threadIdx.x;

    if (bid < 144) {
        // ------------------------- context GEMM -----------------------------
        int h0 = (bid % 6) * CTH;
        int nb = (bid / 6) & 7;
        int b = nb >> 1;
        int n0 = (nb & 1) * CTN;
        int s = bid / 48;
        int l_start = s * 352;
        int iters = (s == 2) ? 10 : 11;           // *32 = 320 / 352

        float* As = pool;                          // [2][64][32]
        float* Bs = pool + 4096;                   // [2][32][128]

        int w = tid >> 5, lane = tid & 31;
        int nw = w * 8;
        int hq = lane * 4;

        const float* attb = g_att + ((size_t)b * EMM + n0) * LL;
        const float* seqb = seq + (size_t)b * LL * HH;

        ull acc[8][2];
#pragma unroll
        for (int i = 0; i < 8; i++) { acc[i][0] = 0ull; acc[i][1] = 0ull; }

        auto loadA = [&](int buf, int l0) {
#pragma unroll
            for (int it = 0; it < 2; it++) {
                int idx = tid + it * 256;
                int n = idx >> 3, l4 = (idx & 7) * 4;
                *(float4*)&As[buf * 2048 + n * 32 + l4] =
                    *(const float4*)&attb[(size_t)n * LL + l0 + l4];
            }
        };
        auto loadB = [&](int buf, int l0) {
#pragma unroll
            for (int it = 0; it < 4; it++) {
                int slot = tid + it * 256;
                int l = slot >> 5, h4 = (slot & 31) * 4;
                *(float4*)&Bs[buf * 4096 + l * 128 + h4] =
                    *(const float4*)&seqb[(size_t)(l0 + l) * HH + h0 + h4];
            }
        };

        loadA(0, l_start);
        loadB(0, l_start);
        __syncthreads();

        for (int c = 0; c < iters; c++) {
            int cur = c & 1;
            if (c + 1 < iters) {
                loadA(cur ^ 1, l_start + (c + 1) * CTL);
                loadB(cur ^ 1, l_start + (c + 1) * CTL);
            }
#pragma unroll
            for (int l4 = 0; l4 < CTL / 4; l4++) {
                float4 a4[8];
#pragma unroll
                for (int i = 0; i < 8; i++)
                    a4[i] = *(const float4*)&As[cur * 2048 + (nw + i) * 32 + l4 * 4];
#pragma unroll
                for (int j = 0; j < 4; j++) {
                    ulonglong2 bv =
                        *(const ulonglong2*)&Bs[cur * 4096 + (l4 * 4 + j) * 128 + hq];
#pragma unroll
                    for (int i = 0; i < 8; i++) {
                        float a = (j == 0) ? a4[i].x : (j == 1) ? a4[i].y
                                 : (j == 2) ? a4[i].z : a4[i].w;
                        ull ad = dup2(a);
                        fma2(acc[i][0], ad, bv.x);
                        fma2(acc[i][1], ad, bv.y);
                    }
                }
            }
            __syncthreads();
        }

#pragma unroll
        for (int i = 0; i < 8; i++) {
            float2 f0 = *(float2*)&acc[i][0];
            float2 f1 = *(float2*)&acc[i][1];
            *(float4*)&g_part[s][b][n0 + nw + i][h0 + hq] =
                make_float4(f0.x, f0.y, f1.x, f1.y);
        }
    } else if (bid < 208) {
        // ------------------------- link span pooling ------------------------
        int lk = bid - 144;
        int k = lk & 15, b = lk >> 4;
        int s = lstart[b * KLNK + k] + 1;
        int len = llen[b * KLNK + k] + 1;          // 1..31

        float* part = pool;                         // [32][33]
        float* wsh = pool + 1056;                   // [32]

        int r = tid >> 3;            // 0..31
        int c4 = (tid & 7) * 4;      // 0,4,...,28
        float a0 = 0.f, a1 = 0.f, a2 = 0.f, a3 = 0.f;
        if (r < len) {
            const float* base = att + (size_t)b * NHH * LL * LL
                              + (size_t)(s + r) * LL + s + c4;
#pragma unroll
            for (int h = 0; h < NHH; h++) {
                const float* p = base + (size_t)h * LL * LL;
                a0 += p[0]; a1 += p[1]; a2 += p[2]; a3 += p[3];
            }
        }
        if (c4 + 0 >= len) a0 = 0.f;
        if (c4 + 1 >= len) a1 = 0.f;
        if (c4 + 2 >= len) a2 = 0.f;
        if (c4 + 3 >= len) a3 = 0.f;
        part[r * 33 + c4 + 0] = a0;
        part[r * 33 + c4 + 1] = a1;
        part[r * 33 + c4 + 2] = a2;
        part[r * 33 + c4 + 3] = a3;
        __syncthreads();

        if (tid < 32) {
            float sum = 0.f;
#pragma unroll
            for (int rr = 0; rr < 32; rr++) sum += part[rr * 33 + tid];  // fixed order
            wsh[tid] = sum;          // zeros for c >= len
        }
        __syncthreads();

        float scale = 1.f / (12.f * (float)len);
        const float* seqb = seq + ((size_t)b * LL + s) * HH;
        float* o = out + ((size_t)b * NROWS + 160 + k) * FF;
        for (int f = tid; f < HH; f += 256) {
            float b0 = 0.f, b1 = 0.f, b2 = 0.f, b3 = 0.f;
#pragma unroll
            for (int c = 0; c < 32; c += 4) {
                b0 += wsh[c + 0] * seqb[(size_t)(c + 0) * HH + f];
                b1 += wsh[c + 1] * seqb[(size_t)(c + 1) * HH + f];
                b2 += wsh[c + 2] * seqb[(size_t)(c + 2) * HH + f];
                b3 += wsh[c + 3] * seqb[(size_t)(c + 3) * HH + f];
            }
            o[f] = ((b0 + b1) + (b2 + b3)) * scale;
        }
        if (tid < TYPED) o[HH + tid] = ttab[2 * TYPED + tid];   // type 2
    } else {
        // ------------------------- node bank rows 0..159 --------------------
        int i = bid - 208;
        int r2 = i % 160, b = i / 160;
        float* o = out + ((size_t)b * NROWS + r2) * FF;

        if (r2 < EE) {
            const int* mp = mpos + (b * EE + r2) * MPE;
            int p0 = mp[0] + 1, p1 = mp[1] + 1, p2 = mp[2] + 1, p3 = mp[3] + 1;
            if (tid < 192) {
                int f = tid * 4;
                float4 x0 = *(const float4*)(seq + ((size_t)b * LL + p0) * HH + f);
                float4 x1 = *(const float4*)(seq + ((size_t)b * LL + p1) * HH + f);
                float4 x2 = *(const float4*)(seq + ((size_t)b * LL + p2) * HH + f);
                float4 x3 = *(const float4*)(seq + ((size_t)b * LL + p3) * HH + f);
                float4 res;
                float m0 = fmaxf(fmaxf(x0.x, x1.x), fmaxf(x2.x, x3.x));
                res.x = m0 + logf(expf(x0.x-m0)+expf(x1.x-m0)+expf(x2.x-m0)+expf(x3.x-m0));
                float m1 = fmaxf(fmaxf(x0.y, x1.y), fmaxf(x2.y, x3.y));
                res.y = m1 + logf(expf(x0.y-m1)+expf(x1.y-m1)+expf(x2.y-m1)+expf(x3.y-m1));
                float m2 = fmaxf(fmaxf(x0.z, x1.z), fmaxf(x2.z, x3.z));
                res.z = m2 + logf(expf(x0.z-m2)+expf(x1.z-m2)+expf(x2.z-m2)+expf(x3.z-m2));
                float m3 = fmaxf(fmaxf(x0.w, x1.w), fmaxf(x2.w, x3.w));
                res.w = m3 + logf(expf(x0.w-m3)+expf(x1.w-m3)+expf(x2.w-m3)+expf(x3.w-m3));
                *(float4*)(o + f) = res;
            } else if (tid < 192 + TYPED) {
                o[HH + tid - 192] = ttab[tid - 192];              // type 0
            }
        } else {
            int m = r2 - EE;
            int p = mpos[b * EMM + m] + 1;
            if (tid < 192) {
                *(float4*)(o + tid * 4) =
                    *(const float4*)(seq + ((size_t)b * LL + p) * HH + tid * 4);
            } else if (tid < 192 + TYPED) {
                o[HH + tid - 192] = ttab[TYPED + tid - 192];      // type 1
            }
        }
    }
}

// ---------------------------------------------------------------------------
// K3 epilogue: reduce split-K partials (fixed order), normalize, write ctx.
// ---------------------------------------------------------------------------
__global__ void __launch_bounds__(224) k_epi(float* __restrict__ out) {
    int r = blockIdx.x % NA;
    int b = blockIdx.x / NA;
    int tid = threadIdx.x;
    float* o = out + ((size_t)b * NROWS + 176 + r) * FF;

    if (tid < 192) {
        int f = tid * 4;
        float4 v = make_float4(0.f, 0.f, 0.f, 0.f);
        float scale;
        if (r < EE) {
#pragma unroll
            for (int s = 0; s < 3; s++)
#pragma unroll
                for (int mp = 0; mp < MPE; mp++) {
                    float4 p = *(const float4*)&g_part[s][b][r * MPE + mp][f];
                    v.x += p.x; v.y += p.y; v.z += p.z; v.w += p.w;
                }
            const float* rs = g_rs + b * EMM + r * MPE;
            scale = 1.f / ((((rs[0] + rs[1]) + rs[2]) + rs[3]) + 4e-5f);
        } else {
            int m = r - EE;
#pragma unroll
            for (int s = 0; s < 3; s++) {
                float4 p = *(const float4*)&g_part[s][b][m][f];
                v.x += p.x; v.y += p.y; v.z += p.z; v.w += p.w;
            }
            scale = 1.f / (g_rs[b * EMM + m] + 1e-5f);
        }
        *(float4*)(o + f) = make_float4(v.x * scale, v.y * scale, v.z * scale, v.w * scale);
    } else if (tid < 192 + TYPED) {
        o[HH + tid - 192] = 0.f;
    }
}

// ---------------------------------------------------------------------------
extern "C" void kernel_launch(void* const* d_in, const int* in_sizes, int n_in,
                              void* d_out, int out_size) {
    const float* seq    = (const float*)d_in[0];
    const float* att    = (const float*)d_in[1];
    const float* ttab   = (const float*)d_in[2];
    const int*   mpos   = (const int*)d_in[3];
    const int*   lstart = (const int*)d_in[4];
    const int*   llen   = (const int*)d_in[5];
    float* out = (float*)d_out;

    k_ment<<<BB * EMM, 256>>>(att, mpos);
    k_main<<<144 + 64 + 640, 256>>>(att, seq, ttab, mpos, lstart, llen, out);
    k_epi<<<NA * BB, 224>>>(out);
}

// round 8
// speedup vs baseline: 1.2808x; 1.2808x over previous
#include <cuda_runtime.h>
#include <math.h>

#define BB 4
#define LL 1024
#define HH 768
#define NHH 12
#define EE 32
#define MPE 4
#define EMM 128
#define KLNK 16
#define TYPED 20
#define NROWS 336
#define FF (HH + TYPED)      // 788
#define NA 160

typedef unsigned long long ull;

// scratch
__device__ float g_att[BB * EMM * LL];          // mention head-mean att rows
__device__ float g_rs2[BB * EMM * 2];           // per-half row sums
__device__ float g_part[3][BB][EMM][HH];        // split-K raw GEMM partials

__device__ __forceinline__ void fma2(ull& d, ull a, ull b) {
    asm("fma.rn.f32x2 %0, %1, %2, %0;" : "+l"(d) : "l"(a), "l"(b));
}
__device__ __forceinline__ ull dup2(float a) {
    ull d;
    asm("mov.b64 %0, {%1, %1};" : "=l"(d) : "f"(a));
    return d;
}

// ---------------------------------------------------------------------------
// K1 "front": mention half-rows [0,1024) + link [1024,1088) + nodes [1088,1728)
// Mention blocks first: they gate k_ctx.
// ---------------------------------------------------------------------------
__global__ void __launch_bounds__(256) k_front(
    const float* __restrict__ att, const float* __restrict__ seq,
    const float* __restrict__ ttab, const int* __restrict__ mpos,
    const int* __restrict__ lstart, const int* __restrict__ llen,
    float* __restrict__ out)
{
    __shared__ float part[32][33];   // link scratch (also holds red[8])
    __shared__ float wsh[32];
    int bid = blockIdx.x;
    int tid = threadIdx.x;

    if (bid < 1024) {
        // ------- mention attention half-row (head mean) + half rowsum -------
        int b = bid >> 8;
        int m = (bid >> 1) & 127;
        int half = bid & 1;
        int p = mpos[b * EMM + m] + 1;
        int l = half * 512 + tid * 2;
        const float* rp = att + (size_t)b * NHH * LL * LL + (size_t)p * LL + l;

        float2 acc = make_float2(0.f, 0.f);
#pragma unroll
        for (int h = 0; h < NHH; h++) {
            float2 v = *(const float2*)(rp + (size_t)h * LL * LL);
            acc.x += v.x; acc.y += v.y;
        }
        const float inv12 = 1.f / 12.f;
        acc.x *= inv12; acc.y *= inv12;
        *(float2*)&g_att[((size_t)b * EMM + m) * LL + l] = acc;

        float s = acc.x + acc.y;
#pragma unroll
        for (int off = 16; off > 0; off >>= 1)
            s += __shfl_down_sync(0xffffffffu, s, off);
        if ((tid & 31) == 0) wsh[tid >> 5] = s;
        __syncthreads();
        if (tid == 0) {
            float t = 0.f;
#pragma unroll
            for (int ww = 0; ww < 8; ww++) t += wsh[ww];        // fixed order
            g_rs2[(b * EMM + m) * 2 + half] = t;
        }
    } else if (bid < 1088) {
        // ------------------------- link span pooling ------------------------
        int lk = bid - 1024;
        int k = lk & 15, b = lk >> 4;
        int s = lstart[b * KLNK + k] + 1;
        int len = llen[b * KLNK + k] + 1;          // 1..31

        int r = tid >> 3;            // 0..31
        int c4 = (tid & 7) * 4;      // 0,4,...,28
        float a0 = 0.f, a1 = 0.f, a2 = 0.f, a3 = 0.f;
        if (r < len) {
            const float* base = att + (size_t)b * NHH * LL * LL
                              + (size_t)(s + r) * LL + s + c4;
#pragma unroll
            for (int h = 0; h < NHH; h++) {
                const float* p = base + (size_t)h * LL * LL;
                a0 += p[0]; a1 += p[1]; a2 += p[2]; a3 += p[3];
            }
        }
        if (c4 + 0 >= len) a0 = 0.f;
        if (c4 + 1 >= len) a1 = 0.f;
        if (c4 + 2 >= len) a2 = 0.f;
        if (c4 + 3 >= len) a3 = 0.f;
        part[r][c4 + 0] = a0;
        part[r][c4 + 1] = a1;
        part[r][c4 + 2] = a2;
        part[r][c4 + 3] = a3;
        __syncthreads();

        if (tid < 32) {
            float sum = 0.f;
#pragma unroll
            for (int rr = 0; rr < 32; rr++) sum += part[rr][tid];   // fixed order
            wsh[tid] = sum;          // zeros for c >= len
        }
        __syncthreads();

        float scale = 1.f / (12.f * (float)len);
        const float* seqb = seq + ((size_t)b * LL + s) * HH;
        float* o = out + ((size_t)b * NROWS + 160 + k) * FF;
        for (int f = tid; f < HH; f += 256) {
            float b0 = 0.f, b1 = 0.f, b2 = 0.f, b3 = 0.f;
#pragma unroll
            for (int c = 0; c < 32; c += 4) {
                b0 += wsh[c + 0] * seqb[(size_t)(c + 0) * HH + f];
                b1 += wsh[c + 1] * seqb[(size_t)(c + 1) * HH + f];
                b2 += wsh[c + 2] * seqb[(size_t)(c + 2) * HH + f];
                b3 += wsh[c + 3] * seqb[(size_t)(c + 3) * HH + f];
            }
            o[f] = ((b0 + b1) + (b2 + b3)) * scale;
        }
        if (tid < TYPED) o[HH + tid] = ttab[2 * TYPED + tid];   // type 2
    } else {
        // ------------------------- node bank rows 0..159 --------------------
        int i = bid - 1088;
        int r2 = i % 160, b = i / 160;
        float* o = out + ((size_t)b * NROWS + r2) * FF;

        if (r2 < EE) {
            const int* mp = mpos + (b * EE + r2) * MPE;
            int p0 = mp[0] + 1, p1 = mp[1] + 1, p2 = mp[2] + 1, p3 = mp[3] + 1;
            if (tid < 192) {
                int f = tid * 4;
                float4 x0 = *(const float4*)(seq + ((size_t)b * LL + p0) * HH + f);
                float4 x1 = *(const float4*)(seq + ((size_t)b * LL + p1) * HH + f);
                float4 x2 = *(const float4*)(seq + ((size_t)b * LL + p2) * HH + f);
                float4 x3 = *(const float4*)(seq + ((size_t)b * LL + p3) * HH + f);
                float4 res;
                float m0 = fmaxf(fmaxf(x0.x, x1.x), fmaxf(x2.x, x3.x));
                res.x = m0 + logf(expf(x0.x-m0)+expf(x1.x-m0)+expf(x2.x-m0)+expf(x3.x-m0));
                float m1 = fmaxf(fmaxf(x0.y, x1.y), fmaxf(x2.y, x3.y));
                res.y = m1 + logf(expf(x0.y-m1)+expf(x1.y-m1)+expf(x2.y-m1)+expf(x3.y-m1));
                float m2 = fmaxf(fmaxf(x0.z, x1.z), fmaxf(x2.z, x3.z));
                res.z = m2 + logf(expf(x0.z-m2)+expf(x1.z-m2)+expf(x2.z-m2)+expf(x3.z-m2));
                float m3 = fmaxf(fmaxf(x0.w, x1.w), fmaxf(x2.w, x3.w));
                res.w = m3 + logf(expf(x0.w-m3)+expf(x1.w-m3)+expf(x2.w-m3)+expf(x3.w-m3));
                *(float4*)(o + f) = res;
            } else if (tid < 192 + TYPED) {
                o[HH + tid - 192] = ttab[tid - 192];              // type 0
            }
        } else {
            int m = r2 - EE;
            int p = mpos[b * EMM + m] + 1;
            if (tid < 192) {
                *(float4*)(o + tid * 4) =
                    *(const float4*)(seq + ((size_t)b * LL + p) * HH + tid * 4);
            } else if (tid < 192 + TYPED) {
                o[HH + tid - 192] = ttab[TYPED + tid - 192];      // type 1
            }
        }
    }
}

// ---------------------------------------------------------------------------
// K2: split-K raw context GEMM over MENTION rows only (f32x2 FMA).
// Tile: 64n x 128h, TL=32, 256 thr. Warp = 8 n-rows, lane = 4 h.
// Grid (6, 8, 3): h-blocks x (b,n0) x l-chunks {352,352,320} = 144 blocks.
// ---------------------------------------------------------------------------
#define CTN 64
#define CTH 128
#define CTL 32
__global__ void __launch_bounds__(256, 1) k_ctx(const float* __restrict__ seq) {
    int h0 = blockIdx.x * CTH;
    int nb = blockIdx.y;
    int b = nb >> 1;
    int n0 = (nb & 1) * CTN;
    int s = blockIdx.z;
    int l_start = s * 352;
    int iters = (s == 2) ? 10 : 11;

    __shared__ float As[2][CTN][CTL];
    __shared__ float Bs[2][CTL][CTH];

    int tid = threadIdx.x;
    int w = tid >> 5, lane = tid & 31;
    int nw = w * 8;
    int hq = lane * 4;

    const float* attb = g_att + ((size_t)b * EMM + n0) * LL;
    const float* seqb = seq + (size_t)b * LL * HH;

    ull acc[8][2];
#pragma unroll
    for (int i = 0; i < 8; i++) { acc[i][0] = 0ull; acc[i][1] = 0ull; }

    auto loadA = [&](int buf, int l0) {
#pragma unroll
        for (int it = 0; it < 2; it++) {
            int idx = tid + it * 256;
            int n = idx >> 3, l4 = (idx & 7) * 4;
            *(float4*)&As[buf][n][l4] = *(const float4*)&attb[(size_t)n * LL + l0 + l4];
        }
    };
    auto loadB = [&](int buf, int l0) {
#pragma unroll
        for (int it = 0; it < 4; it++) {
            int slot = tid + it * 256;
            int l = slot >> 5, h4 = (slot & 31) * 4;
            *(float4*)&Bs[buf][l][h4] = *(const float4*)&seqb[(size_t)(l0 + l) * HH + h0 + h4];
        }
    };

    loadA(0, l_start);
    loadB(0, l_start);
    __syncthreads();

    for (int c = 0; c < iters; c++) {
        int cur = c & 1;
        if (c + 1 < iters) {
            loadA(cur ^ 1, l_start + (c + 1) * CTL);
            loadB(cur ^ 1, l_start + (c + 1) * CTL);
        }
#pragma unroll
        for (int l4 = 0; l4 < CTL / 4; l4++) {
            float4 a4[8];
#pragma unroll
            for (int i = 0; i < 8; i++)
                a4[i] = *(const float4*)&As[cur][nw + i][l4 * 4];
#pragma unroll
            for (int j = 0; j < 4; j++) {
                ulonglong2 bv = *(const ulonglong2*)&Bs[cur][l4 * 4 + j][hq];
#pragma unroll
                for (int i = 0; i < 8; i++) {
                    float a = (j == 0) ? a4[i].x : (j == 1) ? a4[i].y
                             : (j == 2) ? a4[i].z : a4[i].w;
                    ull ad = dup2(a);
                    fma2(acc[i][0], ad, bv.x);
                    fma2(acc[i][1], ad, bv.y);
                }
            }
        }
        __syncthreads();
    }

#pragma unroll
    for (int i = 0; i < 8; i++) {
        float2 f0 = *(float2*)&acc[i][0];
        float2 f1 = *(float2*)&acc[i][1];
        *(float4*)&g_part[s][b][n0 + nw + i][h0 + hq] =
            make_float4(f0.x, f0.y, f1.x, f1.y);
    }
}

// ---------------------------------------------------------------------------
// K3 epilogue: reduce split-K partials + half rowsums (fixed order),
// normalize, write ctx rows + zero pad.
// ---------------------------------------------------------------------------
__global__ void __launch_bounds__(224) k_epi(float* __restrict__ out) {
    int r = blockIdx.x % NA;
    int b = blockIdx.x / NA;
    int tid = threadIdx.x;
    float* o = out + ((size_t)b * NROWS + 176 + r) * FF;

    if (tid < 192) {
        int f = tid * 4;
        float4 v = make_float4(0.f, 0.f, 0.f, 0.f);
        float scale;
        if (r < EE) {
#pragma unroll
            for (int s = 0; s < 3; s++)
#pragma unroll
                for (int mp = 0; mp < MPE; mp++) {
                    float4 p = *(const float4*)&g_part[s][b][r * MPE + mp][f];
                    v.x += p.x; v.y += p.y; v.z += p.z; v.w += p.w;
                }
            const float* rs = g_rs2 + (b * EMM + r * MPE) * 2;
            float t = 0.f;
#pragma unroll
            for (int q = 0; q < 8; q++) t += rs[q];              // fixed order
            scale = 1.f / (t + 4e-5f);
        } else {
            int m = r - EE;
#pragma unroll
            for (int s = 0; s < 3; s++) {
                float4 p = *(const float4*)&g_part[s][b][m][f];
                v.x += p.x; v.y += p.y; v.z += p.z; v.w += p.w;
            }
            float t = g_rs2[(b * EMM + m) * 2] + g_rs2[(b * EMM + m) * 2 + 1];
            scale = 1.f / (t + 1e-5f);
        }
        *(float4*)(o + f) = make_float4(v.x * scale, v.y * scale, v.z * scale, v.w * scale);
    } else if (tid < 192 + TYPED) {
        o[HH + tid - 192] = 0.f;
    }
}

// ---------------------------------------------------------------------------
extern "C" void kernel_launch(void* const* d_in, const int* in_sizes, int n_in,
                              void* d_out, int out_size) {
    const float* seq    = (const float*)d_in[0];
    const float* att    = (const float*)d_in[1];
    const float* ttab   = (const float*)d_in[2];
    const int*   mpos   = (const int*)d_in[3];
    const int*   lstart = (const int*)d_in[4];
    const int*   llen   = (const int*)d_in[5];
    float* out = (float*)d_out;

    k_front<<<1024 + 64 + 640, 256>>>(att, seq, ttab, mpos, lstart, llen, out);
    k_ctx<<<dim3(HH / CTH, 2 * BB, 3), 256>>>(seq);
    k_epi<<<NA * BB, 224>>>(out);
}

// round 9
// speedup vs baseline: 1.2919x; 1.0086x over previous
#include <cuda_runtime.h>
#include <math.h>

#define BB 4
#define LL 1024
#define HH 768
#define NHH 12
#define EE 32
#define MPE 4
#define EMM 128
#define KLNK 16
#define TYPED 20
#define NROWS 336
#define FF (HH + TYPED)      // 788
#define NA 160
#define NSPLIT 6

typedef unsigned long long ull;

// scratch
__device__ float g_att[BB * EMM * LL];              // mention head-mean att rows
__device__ float g_rs[BB * EMM];                    // mention row sums
__device__ float g_part[NSPLIT][BB][EMM][HH];       // split-K raw GEMM partials

__device__ __forceinline__ void fma2(ull& d, ull a, ull b) {
    asm("fma.rn.f32x2 %0, %1, %2, %0;" : "+l"(d) : "l"(a), "l"(b));
}
__device__ __forceinline__ ull dup2(float a) {
    ull d;
    asm("mov.b64 %0, {%1, %1};" : "=l"(d) : "f"(a));
    return d;
}

// ---------------------------------------------------------------------------
// K1 "front": link-span pooling + mention attention rows + node bank.
// Block roles: [0,64) link, [64,576) mention, [576,1216) nodes.  (R6 proven)
// ---------------------------------------------------------------------------
__global__ void __launch_bounds__(256) k_front(
    const float* __restrict__ att, const float* __restrict__ seq,
    const float* __restrict__ ttab, const int* __restrict__ mpos,
    const int* __restrict__ lstart, const int* __restrict__ llen,
    float* __restrict__ out)
{
    __shared__ float part[32][33];   // [r][c] span partials (padded)
    __shared__ float wsh[32];
    __shared__ float red[8];
    int bid = blockIdx.x;
    int tid = threadIdx.x;

    if (bid < 64) {
        // ---------------- link span pooling (static-MLP) --------------------
        int k = bid & 15, b = bid >> 4;
        int s = lstart[b * KLNK + k] + 1;
        int len = llen[b * KLNK + k] + 1;          // 1..31

        int r = tid >> 3;            // 0..31
        int c4 = (tid & 7) * 4;      // 0,4,...,28
        float a0 = 0.f, a1 = 0.f, a2 = 0.f, a3 = 0.f;
        if (r < len) {
            const float* base = att + (size_t)b * NHH * LL * LL
                              + (size_t)(s + r) * LL + s + c4;
#pragma unroll
            for (int h = 0; h < NHH; h++) {
                const float* p = base + (size_t)h * LL * LL;
                a0 += p[0]; a1 += p[1]; a2 += p[2]; a3 += p[3];
            }
        }
        if (c4 + 0 >= len) a0 = 0.f;
        if (c4 + 1 >= len) a1 = 0.f;
        if (c4 + 2 >= len) a2 = 0.f;
        if (c4 + 3 >= len) a3 = 0.f;
        part[r][c4 + 0] = a0;
        part[r][c4 + 1] = a1;
        part[r][c4 + 2] = a2;
        part[r][c4 + 3] = a3;
        __syncthreads();

        if (tid < 32) {
            float sum = 0.f;
#pragma unroll
            for (int rr = 0; rr < 32; rr++) sum += part[rr][tid];   // fixed order
            wsh[tid] = sum;          // zeros for c >= len
        }
        __syncthreads();

        float scale = 1.f / (12.f * (float)len);
        const float* seqb = seq + ((size_t)b * LL + s) * HH;
        float* o = out + ((size_t)b * NROWS + 160 + k) * FF;
        for (int f = tid; f < HH; f += 256) {
            float b0 = 0.f, b1 = 0.f, b2 = 0.f, b3 = 0.f;
#pragma unroll
            for (int c = 0; c < 32; c += 4) {
                b0 += wsh[c + 0] * seqb[(size_t)(c + 0) * HH + f];
                b1 += wsh[c + 1] * seqb[(size_t)(c + 1) * HH + f];
                b2 += wsh[c + 2] * seqb[(size_t)(c + 2) * HH + f];
                b3 += wsh[c + 3] * seqb[(size_t)(c + 3) * HH + f];
            }
            o[f] = ((b0 + b1) + (b2 + b3)) * scale;
        }
        if (tid < TYPED) o[HH + tid] = ttab[2 * TYPED + tid];   // type 2
    } else if (bid < 576) {
        // ---------------- mention attention row (head mean) + rowsum --------
        int i = bid - 64;
        int m = i & 127, b = i >> 7;
        int p = mpos[b * EMM + m] + 1;
        const float* rp = att + (size_t)b * NHH * LL * LL + (size_t)p * LL + tid * 4;

        float4 acc = make_float4(0.f, 0.f, 0.f, 0.f);
#pragma unroll
        for (int h = 0; h < NHH; h++) {
            float4 v = *(const float4*)(rp + (size_t)h * LL * LL);
            acc.x += v.x; acc.y += v.y; acc.z += v.z; acc.w += v.w;
        }
        const float inv12 = 1.f / 12.f;
        acc.x *= inv12; acc.y *= inv12; acc.z *= inv12; acc.w *= inv12;
        *(float4*)&g_att[((size_t)b * EMM + m) * LL + tid * 4] = acc;

        float s = (acc.x + acc.y) + (acc.z + acc.w);
#pragma unroll
        for (int off = 16; off > 0; off >>= 1)
            s += __shfl_down_sync(0xffffffffu, s, off);
        if ((tid & 31) == 0) red[tid >> 5] = s;
        __syncthreads();
        if (tid == 0) {
            float t = 0.f;
#pragma unroll
            for (int ww = 0; ww < 8; ww++) t += red[ww];        // fixed order
            g_rs[b * EMM + m] = t;
        }
    } else {
        // ---------------- node bank rows 0..159 ----------------
        int i = bid - 576;
        int r2 = i % 160, b = i / 160;
        float* o = out + ((size_t)b * NROWS + r2) * FF;

        if (r2 < EE) {
            const int* mp = mpos + (b * EE + r2) * MPE;
            int p0 = mp[0] + 1, p1 = mp[1] + 1, p2 = mp[2] + 1, p3 = mp[3] + 1;
            if (tid < 192) {
                int f = tid * 4;
                float4 x0 = *(const float4*)(seq + ((size_t)b * LL + p0) * HH + f);
                float4 x1 = *(const float4*)(seq + ((size_t)b * LL + p1) * HH + f);
                float4 x2 = *(const float4*)(seq + ((size_t)b * LL + p2) * HH + f);
                float4 x3 = *(const float4*)(seq + ((size_t)b * LL + p3) * HH + f);
                float4 res;
                float m0 = fmaxf(fmaxf(x0.x, x1.x), fmaxf(x2.x, x3.x));
                res.x = m0 + logf(expf(x0.x-m0)+expf(x1.x-m0)+expf(x2.x-m0)+expf(x3.x-m0));
                float m1 = fmaxf(fmaxf(x0.y, x1.y), fmaxf(x2.y, x3.y));
                res.y = m1 + logf(expf(x0.y-m1)+expf(x1.y-m1)+expf(x2.y-m1)+expf(x3.y-m1));
                float m2 = fmaxf(fmaxf(x0.z, x1.z), fmaxf(x2.z, x3.z));
                res.z = m2 + logf(expf(x0.z-m2)+expf(x1.z-m2)+expf(x2.z-m2)+expf(x3.z-m2));
                float m3 = fmaxf(fmaxf(x0.w, x1.w), fmaxf(x2.w, x3.w));
                res.w = m3 + logf(expf(x0.w-m3)+expf(x1.w-m3)+expf(x2.w-m3)+expf(x3.w-m3));
                *(float4*)(o + f) = res;
            } else if (tid < 192 + TYPED) {
                o[HH + tid - 192] = ttab[tid - 192];              // type 0
            }
        } else {
            int m = r2 - EE;
            int p = mpos[b * EMM + m] + 1;
            if (tid < 192) {
                *(float4*)(o + tid * 4) =
                    *(const float4*)(seq + ((size_t)b * LL + p) * HH + tid * 4);
            } else if (tid < 192 + TYPED) {
                o[HH + tid - 192] = ttab[TYPED + tid - 192];      // type 1
            }
        }
    }
}

// ---------------------------------------------------------------------------
// K2: split-K raw context GEMM (f32x2, n-pair packed, transposed A tile).
// Tile 64n x 128h, TL=32, 256 thr. Warp = 8 n (4 pairs), lane = 4 h.
// Grid (6, 8, 6) = 288 blocks; l-chunks: 4x192 + 2x128.
// ---------------------------------------------------------------------------
#define CTN 64
#define CTH 128
#define CTL 32
__global__ void __launch_bounds__(256, 2) k_ctx(const float* __restrict__ seq) {
    int h0 = blockIdx.x * CTH;
    int nb = blockIdx.y;
    int b = nb >> 1;
    int n0 = (nb & 1) * CTN;
    int s = blockIdx.z;
    int l_start = (s < 4) ? s * 192 : 768 + (s - 4) * 128;
    int iters = (s < 4) ? 6 : 4;

    __shared__ float As[2][CTL * CTN];   // [l][n] transposed
    __shared__ float Bs[2][CTL * CTH];   // [l][h]

    int tid = threadIdx.x;
    int w = tid >> 5, lane = tid & 31;
    int nw = w * 8;
    int hq = lane * 4;

    const float* attb = g_att + ((size_t)b * EMM + n0) * LL;
    const float* seqb = seq + (size_t)b * LL * HH;

    ull acc[4][4];   // [n-pair][h]
#pragma unroll
    for (int p = 0; p < 4; p++)
#pragma unroll
        for (int j = 0; j < 4; j++) acc[p][j] = 0ull;

    auto loadA = [&](int buf, int l0) {
#pragma unroll
        for (int it = 0; it < 2; it++) {
            int idx = tid + it * 256;          // 512 float4 slots
            int n = idx >> 3, l4 = (idx & 7) * 4;
            float4 v = *(const float4*)&attb[(size_t)n * LL + l0 + l4];
            As[buf][(l4 + 0) * CTN + n] = v.x;
            As[buf][(l4 + 1) * CTN + n] = v.y;
            As[buf][(l4 + 2) * CTN + n] = v.z;
            As[buf][(l4 + 3) * CTN + n] = v.w;
        }
    };
    auto loadB = [&](int buf, int l0) {
#pragma unroll
        for (int it = 0; it < 4; it++) {
            int slot = tid + it * 256;
            int l = slot >> 5, h4 = (slot & 31) * 4;
            *(float4*)&Bs[buf][l * CTH + h4] =
                *(const float4*)&seqb[(size_t)(l0 + l) * HH + h0 + h4];
        }
    };

    loadA(0, l_start);
    loadB(0, l_start);
    __syncthreads();

    for (int c = 0; c < iters; c++) {
        int cur = c & 1;
        if (c + 1 < iters) {
            loadA(cur ^ 1, l_start + (c + 1) * CTL);
            loadB(cur ^ 1, l_start + (c + 1) * CTL);
        }
#pragma unroll 8
        for (int l = 0; l < CTL; l++) {
            ulonglong2 a01 = *(const ulonglong2*)&As[cur][l * CTN + nw];
            ulonglong2 a23 = *(const ulonglong2*)&As[cur][l * CTN + nw + 4];
            float4 bq = *(const float4*)&Bs[cur][l * CTH + hq];
            ull b0 = dup2(bq.x), b1 = dup2(bq.y), b2 = dup2(bq.z), b3 = dup2(bq.w);
            fma2(acc[0][0], a01.x, b0); fma2(acc[0][1], a01.x, b1);
            fma2(acc[0][2], a01.x, b2); fma2(acc[0][3], a01.x, b3);
            fma2(acc[1][0], a01.y, b0); fma2(acc[1][1], a01.y, b1);
            fma2(acc[1][2], a01.y, b2); fma2(acc[1][3], a01.y, b3);
            fma2(acc[2][0], a23.x, b0); fma2(acc[2][1], a23.x, b1);
            fma2(acc[2][2], a23.x, b2); fma2(acc[2][3], a23.x, b3);
            fma2(acc[3][0], a23.y, b0); fma2(acc[3][1], a23.y, b1);
            fma2(acc[3][2], a23.y, b2); fma2(acc[3][3], a23.y, b3);
        }
        __syncthreads();
    }

#pragma unroll
    for (int p = 0; p < 4; p++) {
        float2 c0 = *(float2*)&acc[p][0];
        float2 c1 = *(float2*)&acc[p][1];
        float2 c2 = *(float2*)&acc[p][2];
        float2 c3 = *(float2*)&acc[p][3];
        int n = n0 + nw + 2 * p;
        *(float4*)&g_part[s][b][n][h0 + hq]     = make_float4(c0.x, c1.x, c2.x, c3.x);
        *(float4*)&g_part[s][b][n + 1][h0 + hq] = make_float4(c0.y, c1.y, c2.y, c3.y);
    }
}

// ---------------------------------------------------------------------------
// K3 epilogue: reduce 6 split-K partials (fixed order), normalize, write ctx.
// ---------------------------------------------------------------------------
__global__ void __launch_bounds__(224) k_epi(float* __restrict__ out) {
    int r = blockIdx.x % NA;
    int b = blockIdx.x / NA;
    int tid = threadIdx.x;
    float* o = out + ((size_t)b * NROWS + 176 + r) * FF;

    if (tid < 192) {
        int f = tid * 4;
        float4 v = make_float4(0.f, 0.f, 0.f, 0.f);
        float scale;
        if (r < EE) {
#pragma unroll
            for (int s = 0; s < NSPLIT; s++)
#pragma unroll
                for (int mp = 0; mp < MPE; mp++) {
                    float4 p = *(const float4*)&g_part[s][b][r * MPE + mp][f];
                    v.x += p.x; v.y += p.y; v.z += p.z; v.w += p.w;
                }
            const float* rs = g_rs + b * EMM + r * MPE;
            scale = 1.f / ((((rs[0] + rs[1]) + rs[2]) + rs[3]) + 4e-5f);
        } else {
            int m = r - EE;
#pragma unroll
            for (int s = 0; s < NSPLIT; s++) {
                float4 p = *(const float4*)&g_part[s][b][m][f];
                v.x += p.x; v.y += p.y; v.z += p.z; v.w += p.w;
            }
            scale = 1.f / (g_rs[b * EMM + m] + 1e-5f);
        }
        *(float4*)(o + f) = make_float4(v.x * scale, v.y * scale, v.z * scale, v.w * scale);
    } else if (tid < 192 + TYPED) {
        o[HH + tid - 192] = 0.f;
    }
}

// ---------------------------------------------------------------------------
extern "C" void kernel_launch(void* const* d_in, const int* in_sizes, int n_in,
                              void* d_out, int out_size) {
    const float* seq    = (const float*)d_in[0];
    const float* att    = (const float*)d_in[1];
    const float* ttab   = (const float*)d_in[2];
    const int*   mpos   = (const int*)d_in[3];
    const int*   lstart = (const int*)d_in[4];
    const int*   llen   = (const int*)d_in[5];
    float* out = (float*)d_out;

    k_front<<<64 + 512 + 640, 256>>>(att, seq, ttab, mpos, lstart, llen, out);
    k_ctx<<<dim3(HH / CTH, 2 * BB, NSPLIT), 256>>>(seq);
    k_epi<<<NA * BB, 224>>>(out);
}

// round 10
// speedup vs baseline: 1.4398x; 1.1145x over previous
#include <cuda_runtime.h>
#include <math.h>

#define BB 4
#define LL 1024
#define HH 768
#define NHH 12
#define EE 32
#define MPE 4
#define EMM 128
#define KLNK 16
#define TYPED 20
#define NROWS 336
#define FF (HH + TYPED)      // 788
#define NA 160
#define NSPLIT 6

typedef unsigned long long ull;

// scratch
__device__ float g_att[BB * EMM * LL];              // mention head-mean att rows
__device__ float g_rs[BB * EMM];                    // mention row sums
__device__ float g_part[NSPLIT][BB][EMM][HH];       // split-K raw GEMM partials

__device__ __forceinline__ void fma2(ull& d, ull a, ull b) {
    asm("fma.rn.f32x2 %0, %1, %2, %0;" : "+l"(d) : "l"(a), "l"(b));
}
__device__ __forceinline__ ull dup2(float a) {
    ull d;
    asm("mov.b64 %0, {%1, %1};" : "=l"(d) : "f"(a));
    return d;
}

// ---------------------------------------------------------------------------
// K1 "front": link-span pooling + mention attention rows + node bank.
// Block roles: [0,64) link, [64,576) mention, [576,1216) nodes.  (proven)
// ---------------------------------------------------------------------------
__global__ void __launch_bounds__(256) k_front(
    const float* __restrict__ att, const float* __restrict__ seq,
    const float* __restrict__ ttab, const int* __restrict__ mpos,
    const int* __restrict__ lstart, const int* __restrict__ llen,
    float* __restrict__ out)
{
    __shared__ float part[32][33];
    __shared__ float wsh[32];
    __shared__ float red[8];
    int bid = blockIdx.x;
    int tid = threadIdx.x;

    if (bid < 64) {
        // ---------------- link span pooling (static-MLP) --------------------
        int k = bid & 15, b = bid >> 4;
        int s = lstart[b * KLNK + k] + 1;
        int len = llen[b * KLNK + k] + 1;          // 1..31

        int r = tid >> 3;
        int c4 = (tid & 7) * 4;
        float a0 = 0.f, a1 = 0.f, a2 = 0.f, a3 = 0.f;
        if (r < len) {
            const float* base = att + (size_t)b * NHH * LL * LL
                              + (size_t)(s + r) * LL + s + c4;
#pragma unroll
            for (int h = 0; h < NHH; h++) {
                const float* p = base + (size_t)h * LL * LL;
                a0 += p[0]; a1 += p[1]; a2 += p[2]; a3 += p[3];
            }
        }
        if (c4 + 0 >= len) a0 = 0.f;
        if (c4 + 1 >= len) a1 = 0.f;
        if (c4 + 2 >= len) a2 = 0.f;
        if (c4 + 3 >= len) a3 = 0.f;
        part[r][c4 + 0] = a0;
        part[r][c4 + 1] = a1;
        part[r][c4 + 2] = a2;
        part[r][c4 + 3] = a3;
        __syncthreads();

        if (tid < 32) {
            float sum = 0.f;
#pragma unroll
            for (int rr = 0; rr < 32; rr++) sum += part[rr][tid];   // fixed order
            wsh[tid] = sum;
        }
        __syncthreads();

        float scale = 1.f / (12.f * (float)len);
        const float* seqb = seq + ((size_t)b * LL + s) * HH;
        float* o = out + ((size_t)b * NROWS + 160 + k) * FF;
        for (int f = tid; f < HH; f += 256) {
            float b0 = 0.f, b1 = 0.f, b2 = 0.f, b3 = 0.f;
#pragma unroll
            for (int c = 0; c < 32; c += 4) {
                b0 += wsh[c + 0] * seqb[(size_t)(c + 0) * HH + f];
                b1 += wsh[c + 1] * seqb[(size_t)(c + 1) * HH + f];
                b2 += wsh[c + 2] * seqb[(size_t)(c + 2) * HH + f];
                b3 += wsh[c + 3] * seqb[(size_t)(c + 3) * HH + f];
            }
            o[f] = ((b0 + b1) + (b2 + b3)) * scale;
        }
        if (tid < TYPED) o[HH + tid] = ttab[2 * TYPED + tid];   // type 2
    } else if (bid < 576) {
        // ---------------- mention attention row (head mean) + rowsum --------
        int i = bid - 64;
        int m = i & 127, b = i >> 7;
        int p = mpos[b * EMM + m] + 1;
        const float* rp = att + (size_t)b * NHH * LL * LL + (size_t)p * LL + tid * 4;

        float4 acc = make_float4(0.f, 0.f, 0.f, 0.f);
#pragma unroll
        for (int h = 0; h < NHH; h++) {
            float4 v = *(const float4*)(rp + (size_t)h * LL * LL);
            acc.x += v.x; acc.y += v.y; acc.z += v.z; acc.w += v.w;
        }
        const float inv12 = 1.f / 12.f;
        acc.x *= inv12; acc.y *= inv12; acc.z *= inv12; acc.w *= inv12;
        *(float4*)&g_att[((size_t)b * EMM + m) * LL + tid * 4] = acc;

        float s = (acc.x + acc.y) + (acc.z + acc.w);
#pragma unroll
        for (int off = 16; off > 0; off >>= 1)
            s += __shfl_down_sync(0xffffffffu, s, off);
        if ((tid & 31) == 0) red[tid >> 5] = s;
        __syncthreads();
        if (tid == 0) {
            float t = 0.f;
#pragma unroll
            for (int ww = 0; ww < 8; ww++) t += red[ww];        // fixed order
            g_rs[b * EMM + m] = t;
        }
    } else {
        // ---------------- node bank rows 0..159 ----------------
        int i = bid - 576;
        int r2 = i % 160, b = i / 160;
        float* o = out + ((size_t)b * NROWS + r2) * FF;

        if (r2 < EE) {
            const int* mp = mpos + (b * EE + r2) * MPE;
            int p0 = mp[0] + 1, p1 = mp[1] + 1, p2 = mp[2] + 1, p3 = mp[3] + 1;
            if (tid < 192) {
                int f = tid * 4;
                float4 x0 = *(const float4*)(seq + ((size_t)b * LL + p0) * HH + f);
                float4 x1 = *(const float4*)(seq + ((size_t)b * LL + p1) * HH + f);
                float4 x2 = *(const float4*)(seq + ((size_t)b * LL + p2) * HH + f);
                float4 x3 = *(const float4*)(seq + ((size_t)b * LL + p3) * HH + f);
                float4 res;
                float m0 = fmaxf(fmaxf(x0.x, x1.x), fmaxf(x2.x, x3.x));
                res.x = m0 + logf(expf(x0.x-m0)+expf(x1.x-m0)+expf(x2.x-m0)+expf(x3.x-m0));
                float m1 = fmaxf(fmaxf(x0.y, x1.y), fmaxf(x2.y, x3.y));
                res.y = m1 + logf(expf(x0.y-m1)+expf(x1.y-m1)+expf(x2.y-m1)+expf(x3.y-m1));
                float m2 = fmaxf(fmaxf(x0.z, x1.z), fmaxf(x2.z, x3.z));
                res.z = m2 + logf(expf(x0.z-m2)+expf(x1.z-m2)+expf(x2.z-m2)+expf(x3.z-m2));
                float m3 = fmaxf(fmaxf(x0.w, x1.w), fmaxf(x2.w, x3.w));
                res.w = m3 + logf(expf(x0.w-m3)+expf(x1.w-m3)+expf(x2.w-m3)+expf(x3.w-m3));
                *(float4*)(o + f) = res;
            } else if (tid < 192 + TYPED) {
                o[HH + tid - 192] = ttab[tid - 192];              // type 0
            }
        } else {
            int m = r2 - EE;
            int p = mpos[b * EMM + m] + 1;
            if (tid < 192) {
                *(float4*)(o + tid * 4) =
                    *(const float4*)(seq + ((size_t)b * LL + p) * HH + tid * 4);
            } else if (tid < 192 + TYPED) {
                o[HH + tid - 192] = ttab[TYPED + tid - 192];      // type 1
            }
        }
    }
}

// ---------------------------------------------------------------------------
// K2: split-K raw context GEMM (R6-proven inner loop, 6-way split for occ 2).
// Tile 64n x 128h, TL=32, 256 thr. Warp = 8 n-rows, lane = 4 h.
// Grid (6, 8, 6) = 288 blocks; l-chunks 192,192,160,160,160,160.
// ---------------------------------------------------------------------------
#define CTN 64
#define CTH 128
#define CTL 32
__global__ void __launch_bounds__(256, 2) k_ctx(const float* __restrict__ seq) {
    int h0 = blockIdx.x * CTH;
    int nb = blockIdx.y;
    int b = nb >> 1;
    int n0 = (nb & 1) * CTN;
    int s = blockIdx.z;
    int l_start = (s < 2) ? s * 192 : 384 + (s - 2) * 160;
    int iters = (s < 2) ? 6 : 5;

    __shared__ float As[2][CTN][CTL];
    __shared__ float Bs[2][CTL][CTH];

    int tid = threadIdx.x;
    int w = tid >> 5, lane = tid & 31;
    int nw = w * 8;
    int hq = lane * 4;

    const float* attb = g_att + ((size_t)b * EMM + n0) * LL;
    const float* seqb = seq + (size_t)b * LL * HH;

    ull acc[8][2];
#pragma unroll
    for (int i = 0; i < 8; i++) { acc[i][0] = 0ull; acc[i][1] = 0ull; }

    auto loadA = [&](int buf, int l0) {
#pragma unroll
        for (int it = 0; it < 2; it++) {
            int idx = tid + it * 256;
            int n = idx >> 3, l4 = (idx & 7) * 4;
            *(float4*)&As[buf][n][l4] = *(const float4*)&attb[(size_t)n * LL + l0 + l4];
        }
    };
    auto loadB = [&](int buf, int l0) {
#pragma unroll
        for (int it = 0; it < 4; it++) {
            int slot = tid + it * 256;
            int l = slot >> 5, h4 = (slot & 31) * 4;
            *(float4*)&Bs[buf][l][h4] = *(const float4*)&seqb[(size_t)(l0 + l) * HH + h0 + h4];
        }
    };

    loadA(0, l_start);
    loadB(0, l_start);
    __syncthreads();

    for (int c = 0; c < iters; c++) {
        int cur = c & 1;
        if (c + 1 < iters) {
            loadA(cur ^ 1, l_start + (c + 1) * CTL);
            loadB(cur ^ 1, l_start + (c + 1) * CTL);
        }
#pragma unroll
        for (int l4 = 0; l4 < CTL / 4; l4++) {
            float4 a4[8];
#pragma unroll
            for (int i = 0; i < 8; i++)
                a4[i] = *(const float4*)&As[cur][nw + i][l4 * 4];
#pragma unroll
            for (int j = 0; j < 4; j++) {
                ulonglong2 bv = *(const ulonglong2*)&Bs[cur][l4 * 4 + j][hq];
#pragma unroll
                for (int i = 0; i < 8; i++) {
                    float a = (j == 0) ? a4[i].x : (j == 1) ? a4[i].y
                             : (j == 2) ? a4[i].z : a4[i].w;
                    ull ad = dup2(a);
                    fma2(acc[i][0], ad, bv.x);
                    fma2(acc[i][1], ad, bv.y);
                }
            }
        }
        __syncthreads();
    }

#pragma unroll
    for (int i = 0; i < 8; i++) {
        float2 f0 = *(float2*)&acc[i][0];
        float2 f1 = *(float2*)&acc[i][1];
        *(float4*)&g_part[s][b][n0 + nw + i][h0 + hq] =
            make_float4(f0.x, f0.y, f1.x, f1.y);
    }
}

// ---------------------------------------------------------------------------
// K3 epilogue: reduce 6 split-K partials (fixed order), normalize, write ctx.
// ---------------------------------------------------------------------------
__global__ void __launch_bounds__(224) k_epi(float* __restrict__ out) {
    int r = blockIdx.x % NA;
    int b = blockIdx.x / NA;
    int tid = threadIdx.x;
    float* o = out + ((size_t)b * NROWS + 176 + r) * FF;

    if (tid < 192) {
        int f = tid * 4;
        float4 v = make_float4(0.f, 0.f, 0.f, 0.f);
        float scale;
        if (r < EE) {
#pragma unroll
            for (int s = 0; s < NSPLIT; s++)
#pragma unroll
                for (int mp = 0; mp < MPE; mp++) {
                    float4 p = *(const float4*)&g_part[s][b][r * MPE + mp][f];
                    v.x += p.x; v.y += p.y; v.z += p.z; v.w += p.w;
                }
            const float* rs = g_rs + b * EMM + r * MPE;
            scale = 1.f / ((((rs[0] + rs[1]) + rs[2]) + rs[3]) + 4e-5f);
        } else {
            int m = r - EE;
#pragma unroll
            for (int s = 0; s < NSPLIT; s++) {
                float4 p = *(const float4*)&g_part[s][b][m][f];
                v.x += p.x; v.y += p.y; v.z += p.z; v.w += p.w;
            }
            scale = 1.f / (g_rs[b * EMM + m] + 1e-5f);
        }
        *(float4*)(o + f) = make_float4(v.x * scale, v.y * scale, v.z * scale, v.w * scale);
    } else if (tid < 192 + TYPED) {
        o[HH + tid - 192] = 0.f;
    }
}

// ---------------------------------------------------------------------------
extern "C" void kernel_launch(void* const* d_in, const int* in_sizes, int n_in,
                              void* d_out, int out_size) {
    const float* seq    = (const float*)d_in[0];
    const float* att    = (const float*)d_in[1];
    const float* ttab   = (const float*)d_in[2];
    const int*   mpos   = (const int*)d_in[3];
    const int*   lstart = (const int*)d_in[4];
    const int*   llen   = (const int*)d_in[5];
    float* out = (float*)d_out;

    k_front<<<64 + 512 + 640, 256>>>(att, seq, ttab, mpos, lstart, llen, out);
    k_ctx<<<dim3(HH / CTH, 2 * BB, NSPLIT), 256>>>(seq);
    k_epi<<<NA * BB, 224>>>(out);
}